// round 15
// baseline (speedup 1.0000x reference)
#include <cuda_runtime.h>
#include <math.h>

// ---------------------------------------------------------------------------
// MS-SSIM on (32,3,512,512) fp32, 5 levels, in (s,d)=(x+y, x-y) basis.
// ssim_big<EXT,TH> (all levels): 32-wide x TH-tall tile, 288 threads (32x9),
//   TH/32 passes; per pass stage-2 = exactly ONE task per thread (36 halo
//   rows x 8 col groups); 19KB hAB band in smem; direct global reads
//   (L1-cached); permuted STS (conflict-free). TH=64 for L0/L1, TH=32 for
//   L2/L3/L4 (more blocks -> better latency hiding). L4 disables pool.
// Reduction: per-block partial stores -> 48-block mid-reduce -> tiny combine.
// ---------------------------------------------------------------------------

#define NC 96
#define L1_PER 65536            // 256*256
#define L2_PER 16384            // 128*128
#define L3_PER 4096             // 64*64
#define L4_PER 1024             // 32*32
#define OFF_L1 0
#define OFF_L2 (NC * L1_PER)
#define OFF_L3 (OFF_L2 + NC * L2_PER)
#define OFF_L4 (OFF_L3 + NC * L3_PER)
#define SD_TOT (OFF_L4 + NC * L4_PER)

#define NPART0 (16 * 8 * NC)    // 12288
#define NPART1 (8 * 4 * NC)     // 3072
#define NPART2 (4 * 4 * NC)     // 1536
#define NPART3 (2 * 2 * NC)     // 384
#define NPART4 NC               // 96

__device__ __align__(16) float2 g_sd[SD_TOT];
__device__ float2 g_part0[NPART0];
__device__ float2 g_part1[NPART1];
__device__ float2 g_part2[NPART2];
__device__ float2 g_part3[NPART3];
__device__ float2 g_part4[NPART4];
__device__ double2 g_mid[48][5];

#define GW0 0.12007838424321349f
#define GW1 0.23388075658535032f
#define GW2 0.29208171834287243f
#define C1V (0.01f * 0.01f)
#define C2V (0.03f * 0.03f)

typedef unsigned long long u64;

__device__ __forceinline__ u64 pk2(float lo, float hi) {
    u64 r; asm("mov.b64 %0, {%1, %2};" : "=l"(r) : "f"(lo), "f"(hi)); return r;
}
__device__ __forceinline__ void upk2(u64 v, float& lo, float& hi) {
    asm("mov.b64 {%0, %1}, %2;" : "=f"(lo), "=f"(hi) : "l"(v));
}
__device__ __forceinline__ u64 fma2_(u64 a, u64 b, u64 c) {
    u64 d; asm("fma.rn.f32x2 %0, %1, %2, %3;" : "=l"(d) : "l"(a), "l"(b), "l"(c)); return d;
}
__device__ __forceinline__ u64 mul2_(u64 a, u64 b) {
    u64 d; asm("mul.rn.f32x2 %0, %1, %2;" : "=l"(d) : "l"(a), "l"(b)); return d;
}
__device__ __forceinline__ u64 add2_(u64 a, u64 b) {
    u64 d; asm("add.rn.f32x2 %0, %1, %2;" : "=l"(d) : "l"(a), "l"(b)); return d;
}
__device__ __forceinline__ float rcpa(float x) {
    float r; asm("rcp.approx.f32 %0, %1;" : "=f"(r) : "f"(x)); return r;
}

__device__ __forceinline__ void ssim_px(u64 mu, u64 sq, float& sa, float& ca)
{
    float ms2, md2; upk2(mul2_(mu, mu), ms2, md2);
    float es, ed;  upk2(sq, es, ed);
    float dm = ms2 - md2;
    float sm = ms2 + md2;
    float lnum = fmaf(0.5f, dm, C1V);
    float lden = fmaf(0.5f, sm, C1V);
    float csn  = fmaf(0.5f, (es - ed) - dm, C2V);
    float csd  = fmaf(0.5f, (es + ed) - sm, C2V);
    float r = rcpa(csd * lden);
    ca = fmaf(csn * lden, r, ca);
    sa = fmaf(csn * lnum, r, sa);
}

// ---------------------------------------------------------------------------
// Big-level kernel: 32-wide x TH-tall tile, 288 threads (32x9).
// smem: hAB[36][33] ulonglong2 = 19008 B (band reused across TH/32 passes).
// ---------------------------------------------------------------------------
template<bool EXT, int TH>
__global__ void __launch_bounds__(288, 5)
ssim_big(const float* __restrict__ ext1, const float* __restrict__ ext2,
         int inOff, int outOff, int W, int H, float2* __restrict__ part)
{
    __shared__ ulonglong2 hAB[36 * 33];
    __shared__ float red[2][9];

    const int tx = threadIdx.x, ty = threadIdx.y;
    const int tid = ty * 32 + tx;           // 0..287
    const int ox = blockIdx.x * 32, oy = blockIdx.y * TH;
    const int plane = blockIdx.z;

    const u64 w0p = pk2(GW0, GW0), w1p = pk2(GW1, GW1), w2p = pk2(GW2, GW2);
    const u64 quarter = pk2(0.25f, 0.25f);

    const size_t planeOff = (size_t)plane * W * H;
    const float2* src = g_sd + inOff + planeOff;   // used when !EXT
    const float* p1 = EXT ? (ext1 + planeOff) : nullptr;
    const float* p2 = EXT ? (ext2 + planeOff) : nullptr;

    // ---- fused 2x2 avg-pool (direct from global; region always in-image) ----
    if (outOff >= 0 && tid < 256) {
        int Wh = W >> 1;
        #pragma unroll
        for (int it = 0; it < TH / 32; it++) {
            int idx = tid + it * 256;
            int pr = idx >> 4, pc2_ = idx & 15;   // 16x(TH/2) pooled outputs
            // remap: 16 col-pairs wide -> pc2 in float2 pairs (2 outputs each)
            int pr2 = idx >> 3, pc2 = idx & 7;
            (void)pr; (void)pc2_;
            size_t o = (size_t)outOff + (size_t)plane * (Wh * (H >> 1))
                     + (size_t)(oy / 2 + pr2) * Wh + (ox / 2) + 2 * pc2;
            if (EXT) {
                const float* q1 = p1 + (size_t)(oy + 2 * pr2) * W + ox + 4 * pc2;
                const float* q2 = p2 + (size_t)(oy + 2 * pr2) * W + ox + 4 * pc2;
                float4 a0 = *reinterpret_cast<const float4*>(q1);
                float4 a1 = *reinterpret_cast<const float4*>(q1 + W);
                float4 b0 = *reinterpret_cast<const float4*>(q2);
                float4 b1 = *reinterpret_cast<const float4*>(q2 + W);
                float sA0 = a0.x + a0.y + a1.x + a1.y;
                float sA1 = a0.z + a0.w + a1.z + a1.w;
                float sB0 = b0.x + b0.y + b1.x + b1.y;
                float sB1 = b0.z + b0.w + b1.z + b1.w;
                float4 outv = make_float4(0.25f * (sA0 + sB0), 0.25f * (sA0 - sB0),
                                          0.25f * (sA1 + sB1), 0.25f * (sA1 - sB1));
                *reinterpret_cast<float4*>(&g_sd[o]) = outv;
            } else {
                const float2* q = src + (size_t)(oy + 2 * pr2) * W + ox + 4 * pc2;
                ulonglong2 A = *reinterpret_cast<const ulonglong2*>(q);
                ulonglong2 B = *reinterpret_cast<const ulonglong2*>(q + 2);
                ulonglong2 C = *reinterpret_cast<const ulonglong2*>(q + W);
                ulonglong2 D = *reinterpret_cast<const ulonglong2*>(q + W + 2);
                ulonglong2 outv;
                outv.x = mul2_(quarter, add2_(add2_(A.x, A.y), add2_(C.x, C.y)));
                outv.y = mul2_(quarter, add2_(add2_(B.x, B.y), add2_(D.x, D.y)));
                *reinterpret_cast<ulonglong2*>(&g_sd[o]) = outv;
            }
        }
    }

    float sacc = 0.f, cacc = 0.f;

    #pragma unroll
    for (int h = 0; h < TH / 32; h++) {
        // ---- stage 2: horizontal moments, exactly ONE task per thread ----
        // task tid = rl*8 + g ; rl in 0..35 (halo rows), g in 0..7 (col group)
        {
            int rl = tid >> 3, g = tid & 7;
            int gy = oy + h * 32 + rl - 2;
            int c0 = ox + 4 * g - 2;             // first needed input col
            u64 v[8];
            if ((gy >= 0) & (gy < H)) {
                if (EXT) {
                    if (c0 >= 2 && c0 + 9 < W) {
                        const float* q1 = p1 + (size_t)gy * W + (c0 - 2);
                        const float* q2 = p2 + (size_t)gy * W + (c0 - 2);
                        float4 A0 = *reinterpret_cast<const float4*>(q1);
                        float4 B0 = *reinterpret_cast<const float4*>(q2);
                        v[0] = pk2(A0.z + B0.z, A0.z - B0.z);
                        v[1] = pk2(A0.w + B0.w, A0.w - B0.w);
                        float4 A1 = *reinterpret_cast<const float4*>(q1 + 4);
                        float4 B1 = *reinterpret_cast<const float4*>(q2 + 4);
                        v[2] = pk2(A1.x + B1.x, A1.x - B1.x);
                        v[3] = pk2(A1.y + B1.y, A1.y - B1.y);
                        v[4] = pk2(A1.z + B1.z, A1.z - B1.z);
                        v[5] = pk2(A1.w + B1.w, A1.w - B1.w);
                        float4 A2 = *reinterpret_cast<const float4*>(q1 + 8);
                        float4 B2 = *reinterpret_cast<const float4*>(q2 + 8);
                        v[6] = pk2(A2.x + B2.x, A2.x - B2.x);
                        v[7] = pk2(A2.y + B2.y, A2.y - B2.y);
                    } else {
                        #pragma unroll
                        for (int e = 0; e < 8; e++) {
                            int c = c0 + e;
                            float av = 0.f, bv = 0.f;
                            if ((c >= 0) & (c < W)) {
                                size_t ix = (size_t)gy * W + c;
                                av = p1[ix]; bv = p2[ix];
                            }
                            v[e] = pk2(av + bv, av - bv);
                        }
                    }
                } else {
                    if (c0 >= 0 && c0 + 8 <= W) {
                        const ulonglong2* q =
                            reinterpret_cast<const ulonglong2*>(src + (size_t)gy * W + c0);
                        ulonglong2 q0 = q[0], q1v = q[1], q2v = q[2], q3v = q[3];
                        v[0] = q0.x;  v[1] = q0.y;
                        v[2] = q1v.x; v[3] = q1v.y;
                        v[4] = q2v.x; v[5] = q2v.y;
                        v[6] = q3v.x; v[7] = q3v.y;
                    } else {
                        #pragma unroll
                        for (int e = 0; e < 8; e++) {
                            int c = c0 + e;
                            v[e] = ((c >= 0) & (c < W))
                                 ? *reinterpret_cast<const u64*>(src + (size_t)gy * W + c)
                                 : 0ull;
                        }
                    }
                }
            } else {
                #pragma unroll
                for (int e = 0; e < 8; e++) v[e] = 0ull;
            }

            u64 vs[8];
            #pragma unroll
            for (int i = 0; i < 8; i++) vs[i] = mul2_(v[i], v[i]);
            #pragma unroll
            for (int o = 0; o < 4; o++) {
                u64 asd = 0ull, asq = 0ull;
                #pragma unroll
                for (int k = 0; k < 5; k++) {
                    u64 wp = (k == 0 || k == 4) ? w0p : ((k == 1 || k == 3) ? w1p : w2p);
                    asd = fma2_(wp, v[o + k], asd);
                    asq = fma2_(wp, vs[o + k], asq);
                }
                // logical col 4g+o stored at physical col g+8o (conflict-free)
                hAB[rl * 33 + g + 8 * o] = make_ulonglong2(asd, asq);
            }
        }
        __syncthreads();

        // ---- stage 3: vertical ring, warps 0-7, 4 output rows per thread ----
        if (ty < 8) {
            const int b = ty * 4;
            ulonglong2 ring[5];
            #pragma unroll
            for (int j = 0; j < 5; j++)
                ring[j] = hAB[(b + j) * 33 + tx];

            #pragma unroll
            for (int i = 0; i < 4; i++) {
                if (i > 0) {
                    int sl = (i + 4) % 5;
                    ring[sl] = hAB[(b + i + 4) * 33 + tx];
                }
                u64 mu = 0ull, sq = 0ull;
                #pragma unroll
                for (int k = 0; k < 5; k++) {
                    int sl = (i + k) % 5;
                    u64 wp = (k == 0 || k == 4) ? w0p : ((k == 1 || k == 3) ? w1p : w2p);
                    mu = fma2_(wp, ring[sl].x, mu);
                    sq = fma2_(wp, ring[sl].y, sq);
                }
                ssim_px(mu, sq, sacc, cacc);
            }
        }
        __syncthreads();
    }

    // ---- reduction -> per-block partial store ----
    #pragma unroll
    for (int off = 16; off; off >>= 1) {
        sacc += __shfl_down_sync(0xffffffffu, sacc, off);
        cacc += __shfl_down_sync(0xffffffffu, cacc, off);
    }
    if (tx == 0) { red[0][ty] = sacc; red[1][ty] = cacc; }
    __syncthreads();
    if (tid == 0) {
        float ss = 0.f, cc = 0.f;
        #pragma unroll
        for (int i = 0; i < 9; i++) { ss += red[0][i]; cc += red[1][i]; }
        int bid = blockIdx.x + gridDim.x * (blockIdx.y + gridDim.y * blockIdx.z);
        part[bid] = make_float2(ss, cc);
    }
}

// ---------------------------------------------------------------------------
// Mid-reduce: 48 blocks x 256 threads; own slot -> no atomics.
// ---------------------------------------------------------------------------
__global__ void __launch_bounds__(256)
mid_reduce()
{
    const int tid = threadIdx.x, bid = blockIdx.x;
    const int lane = tid & 31, warp = tid >> 5;
    const int g = bid * 256 + tid;       // 0..12287
    __shared__ double sh[10][8];

    double s[5] = {0, 0, 0, 0, 0}, c[5] = {0, 0, 0, 0, 0};
    { float2 v = g_part0[g]; s[0] = v.x; c[0] = v.y; }
    if (g < NPART1) { float2 v = g_part1[g]; s[1] = v.x; c[1] = v.y; }
    if (g < NPART2) { float2 v = g_part2[g]; s[2] = v.x; c[2] = v.y; }
    if (g < NPART3) { float2 v = g_part3[g]; s[3] = v.x; c[3] = v.y; }
    if (g < NPART4) { float2 v = g_part4[g]; s[4] = v.x; c[4] = v.y; }

    #pragma unroll
    for (int l = 0; l < 5; l++) {
        double x = s[l], y = c[l];
        #pragma unroll
        for (int off = 16; off; off >>= 1) {
            x += __shfl_down_sync(0xffffffffu, x, off);
            y += __shfl_down_sync(0xffffffffu, y, off);
        }
        if (lane == 0) { sh[l][warp] = x; sh[5 + l][warp] = y; }
    }
    __syncthreads();
    if (tid < 5) {
        double x = 0, y = 0;
        #pragma unroll
        for (int w = 0; w < 8; w++) { x += sh[tid][w]; y += sh[5 + tid][w]; }
        g_mid[bid][tid] = make_double2(x, y);
    }
}

__global__ void __launch_bounds__(64)
final_combine(float* __restrict__ out)
{
    const int tid = threadIdx.x;
    const int lane = tid & 31, warp = tid >> 5;
    __shared__ double sh[10][2];

    double s[5] = {0, 0, 0, 0, 0}, c[5] = {0, 0, 0, 0, 0};
    if (tid < 48) {
        #pragma unroll
        for (int l = 0; l < 5; l++) {
            double2 v = g_mid[tid][l];
            s[l] = v.x; c[l] = v.y;
        }
    }
    #pragma unroll
    for (int l = 0; l < 5; l++) {
        double x = s[l], y = c[l];
        #pragma unroll
        for (int off = 16; off; off >>= 1) {
            x += __shfl_down_sync(0xffffffffu, x, off);
            y += __shfl_down_sync(0xffffffffu, y, off);
        }
        if (lane == 0) { sh[l][warp] = x; sh[5 + l][warp] = y; }
    }
    __syncthreads();
    if (tid == 0) {
        double S[5], C[5];
        #pragma unroll
        for (int l = 0; l < 5; l++) {
            S[l] = sh[l][0] + sh[l][1];
            C[l] = sh[5 + l][0] + sh[5 + l][1];
        }
        const double w[5] = {(double)0.0448f, (double)0.2856f, (double)0.3001f,
                             (double)0.2363f, (double)0.1333f};
        double cnt4 = (double)NC * 32.0 * 32.0;
        double ss4 = (S[4] / cnt4 + 1.0) * 0.5;
        double p2 = pow(ss4, w[4]);

        double res = 1.0;
        #pragma unroll
        for (int i = 0; i < 4; i++) {
            int dim = 512 >> i;
            double cnt = (double)NC * (double)dim * (double)dim;
            double m = (C[i] / cnt + 1.0) * 0.5;
            res *= pow(m, w[i]) * p2;
        }
        out[0] = (float)res;
    }
}

extern "C" void kernel_launch(void* const* d_in, const int* in_sizes, int n_in,
                              void* d_out, int out_size)
{
    const float* img1 = (const float*)d_in[0];
    const float* img2 = (const float*)d_in[1];
    float* out = (float*)d_out;

    float2* part0; cudaGetSymbolAddress((void**)&part0, g_part0);
    float2* part1; cudaGetSymbolAddress((void**)&part1, g_part1);
    float2* part2; cudaGetSymbolAddress((void**)&part2, g_part2);
    float2* part3; cudaGetSymbolAddress((void**)&part3, g_part3);
    float2* part4; cudaGetSymbolAddress((void**)&part4, g_part4);

    dim3 blk(32, 9);
    ssim_big<true, 64><<<dim3(16, 8, NC), blk>>>(img1, img2, 0, OFF_L1, 512, 512, part0);
    ssim_big<false, 64><<<dim3(8, 4, NC), blk>>>(nullptr, nullptr, OFF_L1, OFF_L2, 256, 256, part1);
    ssim_big<false, 32><<<dim3(4, 4, NC), blk>>>(nullptr, nullptr, OFF_L2, OFF_L3, 128, 128, part2);
    ssim_big<false, 32><<<dim3(2, 2, NC), blk>>>(nullptr, nullptr, OFF_L3, OFF_L4, 64, 64, part3);
    ssim_big<false, 32><<<dim3(1, 1, NC), blk>>>(nullptr, nullptr, OFF_L4, -1, 32, 32, part4);
    mid_reduce<<<48, 256>>>();
    final_combine<<<1, 64>>>(out);
}

// round 16
// speedup vs baseline: 1.0765x; 1.0765x over previous
#include <cuda_runtime.h>
#include <math.h>

// ---------------------------------------------------------------------------
// MS-SSIM on (32,3,512,512) fp32, 5 levels, in (s,d)=(x+y, x-y) basis.
// ssim_big<EXT,TH>: 32-wide x TH-tall tile, 288 threads (32x9), TH/32 passes;
//   per pass stage-2 = exactly ONE task per thread (36 halo rows x 8 col
//   groups); 19KB hAB band in smem; direct global reads (L1-cached);
//   permuted STS (conflict-free). Pool: 4*TH ulonglong2 tasks (in-bounds).
//   TH=64 for L0/L1 (proven config), TH=32 for L2/L3/L4. L4 disables pool.
// Reduction: per-block partial stores -> 48-block mid-reduce -> tiny combine.
// ---------------------------------------------------------------------------

#define NC 96
#define L1_PER 65536            // 256*256
#define L2_PER 16384            // 128*128
#define L3_PER 4096             // 64*64
#define L4_PER 1024             // 32*32
#define OFF_L1 0
#define OFF_L2 (NC * L1_PER)
#define OFF_L3 (OFF_L2 + NC * L2_PER)
#define OFF_L4 (OFF_L3 + NC * L3_PER)
#define SD_TOT (OFF_L4 + NC * L4_PER)

#define NPART0 (16 * 8 * NC)    // 12288
#define NPART1 (8 * 4 * NC)     // 3072
#define NPART2 (4 * 4 * NC)     // 1536
#define NPART3 (2 * 2 * NC)     // 384
#define NPART4 NC               // 96

__device__ __align__(16) float2 g_sd[SD_TOT];
__device__ float2 g_part0[NPART0];
__device__ float2 g_part1[NPART1];
__device__ float2 g_part2[NPART2];
__device__ float2 g_part3[NPART3];
__device__ float2 g_part4[NPART4];
__device__ double2 g_mid[48][5];

#define GW0 0.12007838424321349f
#define GW1 0.23388075658535032f
#define GW2 0.29208171834287243f
#define C1V (0.01f * 0.01f)
#define C2V (0.03f * 0.03f)

typedef unsigned long long u64;

__device__ __forceinline__ u64 pk2(float lo, float hi) {
    u64 r; asm("mov.b64 %0, {%1, %2};" : "=l"(r) : "f"(lo), "f"(hi)); return r;
}
__device__ __forceinline__ void upk2(u64 v, float& lo, float& hi) {
    asm("mov.b64 {%0, %1}, %2;" : "=f"(lo), "=f"(hi) : "l"(v));
}
__device__ __forceinline__ u64 fma2_(u64 a, u64 b, u64 c) {
    u64 d; asm("fma.rn.f32x2 %0, %1, %2, %3;" : "=l"(d) : "l"(a), "l"(b), "l"(c)); return d;
}
__device__ __forceinline__ u64 mul2_(u64 a, u64 b) {
    u64 d; asm("mul.rn.f32x2 %0, %1, %2;" : "=l"(d) : "l"(a), "l"(b)); return d;
}
__device__ __forceinline__ u64 add2_(u64 a, u64 b) {
    u64 d; asm("add.rn.f32x2 %0, %1, %2;" : "=l"(d) : "l"(a), "l"(b)); return d;
}
__device__ __forceinline__ float rcpa(float x) {
    float r; asm("rcp.approx.f32 %0, %1;" : "=f"(r) : "f"(x)); return r;
}

__device__ __forceinline__ void ssim_px(u64 mu, u64 sq, float& sa, float& ca)
{
    float ms2, md2; upk2(mul2_(mu, mu), ms2, md2);
    float es, ed;  upk2(sq, es, ed);
    float dm = ms2 - md2;
    float sm = ms2 + md2;
    float lnum = fmaf(0.5f, dm, C1V);
    float lden = fmaf(0.5f, sm, C1V);
    float csn  = fmaf(0.5f, (es - ed) - dm, C2V);
    float csd  = fmaf(0.5f, (es + ed) - sm, C2V);
    float r = rcpa(csd * lden);
    ca = fmaf(csn * lden, r, ca);
    sa = fmaf(csn * lnum, r, sa);
}

// ---------------------------------------------------------------------------
// Big-level kernel: 32-wide x TH-tall tile, 288 threads (32x9).
// smem: hAB[36][33] ulonglong2 = 19008 B (band reused across TH/32 passes).
// ---------------------------------------------------------------------------
template<bool EXT, int TH>
__global__ void __launch_bounds__(288, 5)
ssim_big(const float* __restrict__ ext1, const float* __restrict__ ext2,
         int inOff, int outOff, int W, int H, float2* __restrict__ part)
{
    __shared__ ulonglong2 hAB[36 * 33];
    __shared__ float red[2][9];

    const int tx = threadIdx.x, ty = threadIdx.y;
    const int tid = ty * 32 + tx;           // 0..287
    const int ox = blockIdx.x * 32, oy = blockIdx.y * TH;
    const int plane = blockIdx.z;

    const u64 w0p = pk2(GW0, GW0), w1p = pk2(GW1, GW1), w2p = pk2(GW2, GW2);
    const u64 quarter = pk2(0.25f, 0.25f);

    const size_t planeOff = (size_t)plane * W * H;
    const float2* src = g_sd + inOff + planeOff;   // used when !EXT
    const float* p1 = EXT ? (ext1 + planeOff) : nullptr;
    const float* p2 = EXT ? (ext2 + planeOff) : nullptr;

    // ---- fused 2x2 avg-pool: 4*TH ulonglong2 tasks (in-bounds, one write
    //      per pooled pair). pr in [0, TH/2), pc2 in [0, 8).
    if (outOff >= 0 && tid < 4 * TH) {
        int pr = tid >> 3, pc2 = tid & 7;
        int Wh = W >> 1;
        size_t o = (size_t)outOff + (size_t)plane * (Wh * (H >> 1))
                 + (size_t)(oy / 2 + pr) * Wh + (ox / 2) + 2 * pc2;
        if (EXT) {
            const float* q1 = p1 + (size_t)(oy + 2 * pr) * W + ox + 4 * pc2;
            const float* q2 = p2 + (size_t)(oy + 2 * pr) * W + ox + 4 * pc2;
            float4 a0 = *reinterpret_cast<const float4*>(q1);
            float4 a1 = *reinterpret_cast<const float4*>(q1 + W);
            float4 b0 = *reinterpret_cast<const float4*>(q2);
            float4 b1 = *reinterpret_cast<const float4*>(q2 + W);
            float sA0 = a0.x + a0.y + a1.x + a1.y;
            float sA1 = a0.z + a0.w + a1.z + a1.w;
            float sB0 = b0.x + b0.y + b1.x + b1.y;
            float sB1 = b0.z + b0.w + b1.z + b1.w;
            float4 outv = make_float4(0.25f * (sA0 + sB0), 0.25f * (sA0 - sB0),
                                      0.25f * (sA1 + sB1), 0.25f * (sA1 - sB1));
            *reinterpret_cast<float4*>(&g_sd[o]) = outv;
        } else {
            const float2* q = src + (size_t)(oy + 2 * pr) * W + ox + 4 * pc2;
            ulonglong2 A = *reinterpret_cast<const ulonglong2*>(q);
            ulonglong2 B = *reinterpret_cast<const ulonglong2*>(q + 2);
            ulonglong2 C = *reinterpret_cast<const ulonglong2*>(q + W);
            ulonglong2 D = *reinterpret_cast<const ulonglong2*>(q + W + 2);
            ulonglong2 outv;
            outv.x = mul2_(quarter, add2_(add2_(A.x, A.y), add2_(C.x, C.y)));
            outv.y = mul2_(quarter, add2_(add2_(B.x, B.y), add2_(D.x, D.y)));
            *reinterpret_cast<ulonglong2*>(&g_sd[o]) = outv;
        }
    }

    float sacc = 0.f, cacc = 0.f;

    #pragma unroll
    for (int h = 0; h < TH / 32; h++) {
        // ---- stage 2: horizontal moments, exactly ONE task per thread ----
        // task tid = rl*8 + g ; rl in 0..35 (halo rows), g in 0..7 (col group)
        {
            int rl = tid >> 3, g = tid & 7;
            int gy = oy + h * 32 + rl - 2;
            int c0 = ox + 4 * g - 2;             // first needed input col
            u64 v[8];
            if ((gy >= 0) & (gy < H)) {
                if (EXT) {
                    if (c0 >= 2 && c0 + 9 < W) {
                        const float* q1 = p1 + (size_t)gy * W + (c0 - 2);
                        const float* q2 = p2 + (size_t)gy * W + (c0 - 2);
                        float4 A0 = *reinterpret_cast<const float4*>(q1);
                        float4 B0 = *reinterpret_cast<const float4*>(q2);
                        v[0] = pk2(A0.z + B0.z, A0.z - B0.z);
                        v[1] = pk2(A0.w + B0.w, A0.w - B0.w);
                        float4 A1 = *reinterpret_cast<const float4*>(q1 + 4);
                        float4 B1 = *reinterpret_cast<const float4*>(q2 + 4);
                        v[2] = pk2(A1.x + B1.x, A1.x - B1.x);
                        v[3] = pk2(A1.y + B1.y, A1.y - B1.y);
                        v[4] = pk2(A1.z + B1.z, A1.z - B1.z);
                        v[5] = pk2(A1.w + B1.w, A1.w - B1.w);
                        float4 A2 = *reinterpret_cast<const float4*>(q1 + 8);
                        float4 B2 = *reinterpret_cast<const float4*>(q2 + 8);
                        v[6] = pk2(A2.x + B2.x, A2.x - B2.x);
                        v[7] = pk2(A2.y + B2.y, A2.y - B2.y);
                    } else {
                        #pragma unroll
                        for (int e = 0; e < 8; e++) {
                            int c = c0 + e;
                            float av = 0.f, bv = 0.f;
                            if ((c >= 0) & (c < W)) {
                                size_t ix = (size_t)gy * W + c;
                                av = p1[ix]; bv = p2[ix];
                            }
                            v[e] = pk2(av + bv, av - bv);
                        }
                    }
                } else {
                    if (c0 >= 0 && c0 + 8 <= W) {
                        const ulonglong2* q =
                            reinterpret_cast<const ulonglong2*>(src + (size_t)gy * W + c0);
                        ulonglong2 q0 = q[0], q1v = q[1], q2v = q[2], q3v = q[3];
                        v[0] = q0.x;  v[1] = q0.y;
                        v[2] = q1v.x; v[3] = q1v.y;
                        v[4] = q2v.x; v[5] = q2v.y;
                        v[6] = q3v.x; v[7] = q3v.y;
                    } else {
                        #pragma unroll
                        for (int e = 0; e < 8; e++) {
                            int c = c0 + e;
                            v[e] = ((c >= 0) & (c < W))
                                 ? *reinterpret_cast<const u64*>(src + (size_t)gy * W + c)
                                 : 0ull;
                        }
                    }
                }
            } else {
                #pragma unroll
                for (int e = 0; e < 8; e++) v[e] = 0ull;
            }

            u64 vs[8];
            #pragma unroll
            for (int i = 0; i < 8; i++) vs[i] = mul2_(v[i], v[i]);
            #pragma unroll
            for (int o = 0; o < 4; o++) {
                u64 asd = 0ull, asq = 0ull;
                #pragma unroll
                for (int k = 0; k < 5; k++) {
                    u64 wp = (k == 0 || k == 4) ? w0p : ((k == 1 || k == 3) ? w1p : w2p);
                    asd = fma2_(wp, v[o + k], asd);
                    asq = fma2_(wp, vs[o + k], asq);
                }
                // logical col 4g+o stored at physical col g+8o (conflict-free)
                hAB[rl * 33 + g + 8 * o] = make_ulonglong2(asd, asq);
            }
        }
        __syncthreads();

        // ---- stage 3: vertical ring, warps 0-7, 4 output rows per thread ----
        if (ty < 8) {
            const int b = ty * 4;
            ulonglong2 ring[5];
            #pragma unroll
            for (int j = 0; j < 5; j++)
                ring[j] = hAB[(b + j) * 33 + tx];

            #pragma unroll
            for (int i = 0; i < 4; i++) {
                if (i > 0) {
                    int sl = (i + 4) % 5;
                    ring[sl] = hAB[(b + i + 4) * 33 + tx];
                }
                u64 mu = 0ull, sq = 0ull;
                #pragma unroll
                for (int k = 0; k < 5; k++) {
                    int sl = (i + k) % 5;
                    u64 wp = (k == 0 || k == 4) ? w0p : ((k == 1 || k == 3) ? w1p : w2p);
                    mu = fma2_(wp, ring[sl].x, mu);
                    sq = fma2_(wp, ring[sl].y, sq);
                }
                ssim_px(mu, sq, sacc, cacc);
            }
        }
        __syncthreads();
    }

    // ---- reduction -> per-block partial store ----
    #pragma unroll
    for (int off = 16; off; off >>= 1) {
        sacc += __shfl_down_sync(0xffffffffu, sacc, off);
        cacc += __shfl_down_sync(0xffffffffu, cacc, off);
    }
    if (tx == 0) { red[0][ty] = sacc; red[1][ty] = cacc; }
    __syncthreads();
    if (tid == 0) {
        float ss = 0.f, cc = 0.f;
        #pragma unroll
        for (int i = 0; i < 9; i++) { ss += red[0][i]; cc += red[1][i]; }
        int bid = blockIdx.x + gridDim.x * (blockIdx.y + gridDim.y * blockIdx.z);
        part[bid] = make_float2(ss, cc);
    }
}

// ---------------------------------------------------------------------------
// Mid-reduce: 48 blocks x 256 threads; own slot -> no atomics.
// ---------------------------------------------------------------------------
__global__ void __launch_bounds__(256)
mid_reduce()
{
    const int tid = threadIdx.x, bid = blockIdx.x;
    const int lane = tid & 31, warp = tid >> 5;
    const int g = bid * 256 + tid;       // 0..12287
    __shared__ double sh[10][8];

    double s[5] = {0, 0, 0, 0, 0}, c[5] = {0, 0, 0, 0, 0};
    { float2 v = g_part0[g]; s[0] = v.x; c[0] = v.y; }
    if (g < NPART1) { float2 v = g_part1[g]; s[1] = v.x; c[1] = v.y; }
    if (g < NPART2) { float2 v = g_part2[g]; s[2] = v.x; c[2] = v.y; }
    if (g < NPART3) { float2 v = g_part3[g]; s[3] = v.x; c[3] = v.y; }
    if (g < NPART4) { float2 v = g_part4[g]; s[4] = v.x; c[4] = v.y; }

    #pragma unroll
    for (int l = 0; l < 5; l++) {
        double x = s[l], y = c[l];
        #pragma unroll
        for (int off = 16; off; off >>= 1) {
            x += __shfl_down_sync(0xffffffffu, x, off);
            y += __shfl_down_sync(0xffffffffu, y, off);
        }
        if (lane == 0) { sh[l][warp] = x; sh[5 + l][warp] = y; }
    }
    __syncthreads();
    if (tid < 5) {
        double x = 0, y = 0;
        #pragma unroll
        for (int w = 0; w < 8; w++) { x += sh[tid][w]; y += sh[5 + tid][w]; }
        g_mid[bid][tid] = make_double2(x, y);
    }
}

__global__ void __launch_bounds__(64)
final_combine(float* __restrict__ out)
{
    const int tid = threadIdx.x;
    const int lane = tid & 31, warp = tid >> 5;
    __shared__ double sh[10][2];

    double s[5] = {0, 0, 0, 0, 0}, c[5] = {0, 0, 0, 0, 0};
    if (tid < 48) {
        #pragma unroll
        for (int l = 0; l < 5; l++) {
            double2 v = g_mid[tid][l];
            s[l] = v.x; c[l] = v.y;
        }
    }
    #pragma unroll
    for (int l = 0; l < 5; l++) {
        double x = s[l], y = c[l];
        #pragma unroll
        for (int off = 16; off; off >>= 1) {
            x += __shfl_down_sync(0xffffffffu, x, off);
            y += __shfl_down_sync(0xffffffffu, y, off);
        }
        if (lane == 0) { sh[l][warp] = x; sh[5 + l][warp] = y; }
    }
    __syncthreads();
    if (tid == 0) {
        double S[5], C[5];
        #pragma unroll
        for (int l = 0; l < 5; l++) {
            S[l] = sh[l][0] + sh[l][1];
            C[l] = sh[5 + l][0] + sh[5 + l][1];
        }
        const double w[5] = {(double)0.0448f, (double)0.2856f, (double)0.3001f,
                             (double)0.2363f, (double)0.1333f};
        double cnt4 = (double)NC * 32.0 * 32.0;
        double ss4 = (S[4] / cnt4 + 1.0) * 0.5;
        double p2 = pow(ss4, w[4]);

        double res = 1.0;
        #pragma unroll
        for (int i = 0; i < 4; i++) {
            int dim = 512 >> i;
            double cnt = (double)NC * (double)dim * (double)dim;
            double m = (C[i] / cnt + 1.0) * 0.5;
            res *= pow(m, w[i]) * p2;
        }
        out[0] = (float)res;
    }
}

extern "C" void kernel_launch(void* const* d_in, const int* in_sizes, int n_in,
                              void* d_out, int out_size)
{
    const float* img1 = (const float*)d_in[0];
    const float* img2 = (const float*)d_in[1];
    float* out = (float*)d_out;

    float2* part0; cudaGetSymbolAddress((void**)&part0, g_part0);
    float2* part1; cudaGetSymbolAddress((void**)&part1, g_part1);
    float2* part2; cudaGetSymbolAddress((void**)&part2, g_part2);
    float2* part3; cudaGetSymbolAddress((void**)&part3, g_part3);
    float2* part4; cudaGetSymbolAddress((void**)&part4, g_part4);

    dim3 blk(32, 9);
    ssim_big<true, 64><<<dim3(16, 8, NC), blk>>>(img1, img2, 0, OFF_L1, 512, 512, part0);
    ssim_big<false, 64><<<dim3(8, 4, NC), blk>>>(nullptr, nullptr, OFF_L1, OFF_L2, 256, 256, part1);
    ssim_big<false, 32><<<dim3(4, 4, NC), blk>>>(nullptr, nullptr, OFF_L2, OFF_L3, 128, 128, part2);
    ssim_big<false, 32><<<dim3(2, 2, NC), blk>>>(nullptr, nullptr, OFF_L3, OFF_L4, 64, 64, part3);
    ssim_big<false, 32><<<dim3(1, 1, NC), blk>>>(nullptr, nullptr, OFF_L4, -1, 32, 32, part4);
    mid_reduce<<<48, 256>>>();
    final_combine<<<1, 64>>>(out);
}